// round 8
// baseline (speedup 1.0000x reference)
#include <cuda_runtime.h>
#include <math.h>

#define IMGS  16
#define H     256
#define W     256
#define NPIX  (H * W)            // 65536
#define TOTAL (IMGS * NPIX)      // 1048576
#define BIG2  1.0e12f            // (1e6)^2 for "no opposite pixel in column"
#define BIGF  3.0e37f
#define RWIN  2
#define GUARD 9.0f               // (RWIN+1)^2 exactness guard
#define RPB   8                  // rows per block in the row kernel
#define NROWBLK (IMGS * H / RPB) // 512
#define NWARPS  (NROWBLK * 8)    // 4096 total row-kernel warps

// ---- scratch (static __device__ arrays; allocation-free per harness rules) ----
__device__ float  s_buf[TOTAL];    // signed squared vertical distance: +v^2 (fg) / -v^2 (bg)
__device__ float  d_maxabs[IMGS];
__device__ int    d_counts[IMGS];
__device__ double d_S[IMGS];
__device__ unsigned int d_done;    // warp completion counter for fused finalize

__device__ __forceinline__ float sqrt_approx(float x) {
    float r;
    asm("sqrt.approx.f32 %0, %1;" : "=f"(r) : "f"(x));
    return r;
}

// ---------------------------------------------------------------------------
// Vertical EDT pass (unchanged from R7). 128 blocks x 256 threads: each
// thread owns a 32-row segment of one column; bitmask loads (full MLP),
// clz/ffs segment summaries combined in shared, 32-step unrolled SEL chains.
__global__ void col_pass_kernel(const float* __restrict__ target) {
    __shared__ int sHiF[8][32], sHiB[8][32];
    __shared__ int sLoF[8][32], sLoB[8][32];

    int blk   = blockIdx.x;
    int tid   = threadIdx.x;
    int b     = blk >> 3;
    int chunk = blk & 7;
    int t     = tid & 31;
    int w     = tid >> 5;
    int x     = chunk * 32 + t;
    int ybase = w * 32;

    const float* m = target + b * NPIX + x;
    unsigned word = 0;
    #pragma unroll
    for (int j = 0; j < 32; j++)
        if (m[(ybase + j) * W] > 0.5f) word |= (1u << j);
    int cnt = __popc(word);

    unsigned nw = ~word;
    sHiF[w][t] = word ? (ybase + 31 - __clz(word)) : -1000000;
    sHiB[w][t] = nw   ? (ybase + 31 - __clz(nw))   : -1000000;
    sLoF[w][t] = word ? (ybase + __ffs(word) - 1)  :  1000000;
    sLoB[w][t] = nw   ? (ybase + __ffs(nw) - 1)    :  1000000;
    __syncthreads();

    int lastf = -1000000, lastb = -1000000;
    for (int w2 = 0; w2 < w; w2++) {
        lastf = max(lastf, sHiF[w2][t]);
        lastb = max(lastb, sHiB[w2][t]);
    }
    int nextf = 1000000, nextb = 1000000;
    for (int w2 = w + 1; w2 < 8; w2++) {
        nextf = min(nextf, sLoF[w2][t]);
        nextb = min(nextb, sLoB[w2][t]);
    }

    unsigned pk[16];
    #pragma unroll
    for (int j = 0; j < 32; j++) {
        int  y  = ybase + j;
        bool fg = (word >> j) & 1;
        int  da = y - (fg ? lastb : lastf);
        if (da > 1000) da = 1000;
        if (j & 1) pk[j >> 1] |= ((unsigned)da << 16);
        else       pk[j >> 1]  =  (unsigned)da;
        if (fg) lastf = y; else lastb = y;
    }
    float* sbp = s_buf + b * NPIX + x;
    #pragma unroll
    for (int j = 31; j >= 0; j--) {
        int  y  = ybase + j;
        bool fg = (word >> j) & 1;
        int  db = (fg ? nextb : nextf) - y;
        if (fg) nextf = y; else nextb = y;
        int da = (int)((pk[j >> 1] >> ((j & 1) * 16)) & 0xffffu);
        int d  = min(da, db);
        float v2 = (d > 255) ? BIG2 : (float)(d * d);
        sbp[y * W] = fg ? v2 : -v2;
    }

    #pragma unroll
    for (int o = 16; o; o >>= 1) cnt += __shfl_xor_sync(0xffffffffu, cnt, o);
    if (t == 0) atomicAdd(&d_counts[b], cnt);
}

// ---------------------------------------------------------------------------
// Fused row min-plus + sigmoid + per-image reduction + last-WARP finalize.
// 8 rows per block (one warp per row), 8 pixels per thread. Candidate value
// for pixel of class sign sg:  g_c[q] + k^2 = max(sg*s[q] + k^2, k^2).
// Window |x-q| <= 2, exactness guard 9 (excluded q contribute >= 9);
// edge-replicated halo entries are dominated; rare exact full-row fallback.
// Warps reduce 256 pixels each and atomic straight to per-image accumulators.
__global__ void row_fused_kernel(const float* __restrict__ pred, float* __restrict__ out) {
    int blk  = blockIdx.x;
    int b    = blk >> 5;                 // 32 blocks per image (H/RPB)
    int y0   = (blk & 31) * RPB;
    int tid  = threadIdx.x;
    int r    = tid >> 5;                 // row within block (= warp id): 0..7
    int c    = tid & 31;                 // 8-pixel group within row
    int base = b * NPIX + (y0 + r) * W;
    int x0   = c * 8;

    __shared__ float sh[RPB][W + 8];     // signed s tiles, +4 halo each side

    // front-batched independent loads (MLP 4)
    float4 sa = *(const float4*)(s_buf + base + x0);
    float4 sb = *(const float4*)(s_buf + base + x0 + 4);
    float4 pa = *(const float4*)(pred  + base + x0);
    float4 pb = *(const float4*)(pred  + base + x0 + 4);

    *(float4*)&sh[r][x0 + 4] = sa;
    *(float4*)&sh[r][x0 + 8] = sb;
    if (c == 0)  { sh[r][0] = sa.x; sh[r][1] = sa.x; sh[r][2] = sa.x; sh[r][3] = sa.x; }
    if (c == 31) { sh[r][W+4] = sb.w; sh[r][W+5] = sb.w; sh[r][W+6] = sb.w; sh[r][W+7] = sb.w; }
    __syncthreads();

    // v[i] = sh[r][x0 + i], i=0..15 covers logical x0-4 .. x0+11 (need -2..+9)
    float v[16];
    #pragma unroll
    for (int i = 0; i < 4; i++) {
        float4 a = *(const float4*)&sh[r][x0 + 4 * i];
        v[4*i] = a.x; v[4*i+1] = a.y; v[4*i+2] = a.z; v[4*i+3] = a.w;
    }
    float pr[8] = {pa.x, pa.y, pa.z, pa.w, pb.x, pb.y, pb.z, pb.w};

    float term = 0.f, amax = 0.f;
    #pragma unroll
    for (int p = 0; p < 8; p++) {
        float s_own = v[p + 4];
        float sg    = (s_own > 0.f) ? 1.f : -1.f;       // +1 fg, -1 bg
        float bmin  = BIGF;
        #pragma unroll
        for (int j = 0; j < 5; j++) {                   // q = x + (j-2)
            float kk = (float)((j - 2) * (j - 2));
            bmin = fminf(bmin, fmaxf(fmaf(sg, v[p + 2 + j], kk), kk));
        }
        if (bmin > GUARD) {                             // rare exact full-row fallback
            float xp = (float)(x0 + p);
            bmin = BIGF;
            #pragma unroll 1
            for (int q = 0; q < W; q++) {
                float dx = xp - (float)q;
                float kk = dx * dx;
                bmin = fminf(bmin, fmaxf(fmaf(sg, sh[r][q + 4], kk), kk));
            }
        }
        float sd   = sqrt_approx(bmin);                 // bmin >= 1 always
        amax       = fmaxf(amax, sd);
        float prob = __fdividef(1.f, 1.f + __expf(-pr[p]));
        float sds  = (s_own > 0.f) ? -sd : sd;          // signed distance
        term       = fmaf(prob, sds, term);
    }

    // warp reduction (256 pixels per warp) -> direct global atomics
    #pragma unroll
    for (int o = 16; o; o >>= 1) {
        amax = fmaxf(amax, __shfl_xor_sync(0xffffffffu, amax, o));
        term +=            __shfl_xor_sync(0xffffffffu, term, o);
    }
    int last = 0;
    if (c == 0) {
        atomicMax((int*)&d_maxabs[b], __float_as_int(amax));   // non-neg floats order as ints
        atomicAdd(&d_S[b], (double)term);
        __threadfence();
        unsigned int old = atomicAdd(&d_done, 1u);
        last = (old == (unsigned)(NWARPS - 1)) ? 1 : 0;
    }
    last = __shfl_sync(0xffffffffu, last, 0);

    if (last) {   // unique final warp: finalize + reset replay state
        __threadfence();
        double contrib = 0.0;
        if (c < IMGS) {
            int    cc = __ldcg(&d_counts[c]);
            float  mx = __ldcg(&d_maxabs[c]);
            double S  = __ldcg(&d_S[c]);
            if (cc > 0 && cc < NPIX)
                contrib = S / ((double)mx + 1e-6);
        }
        #pragma unroll
        for (int o = 16; o; o >>= 1)
            contrib += __shfl_xor_sync(0xffffffffu, contrib, o);
        if (c == 0) *out = (float)(contrib / (double)TOTAL);

        if (c < IMGS) { d_S[c] = 0.0; d_maxabs[c] = 0.0f; d_counts[c] = 0; }
        if (c == 0)   d_done = 0u;
    }
}

// ---------------------------------------------------------------------------
extern "C" void kernel_launch(void* const* d_in, const int* in_sizes, int n_in,
                              void* d_out, int out_size) {
    const float* pred   = (const float*)d_in[0];
    const float* target = (const float*)d_in[1];
    float* out = (float*)d_out;

    col_pass_kernel<<<IMGS * 8, 256>>>(target);
    row_fused_kernel<<<NROWBLK, 256>>>(pred, out);
}

// round 9
// speedup vs baseline: 1.1805x; 1.1805x over previous
#include <cuda_runtime.h>
#include <math.h>

#define IMGS  16
#define H     256
#define W     256
#define NPIX  (H * W)            // 65536
#define TOTAL (IMGS * NPIX)      // 1048576
#define BIG2  1.0e12f            // (1e6)^2 for "no opposite pixel in column"
#define BIGF  3.0e37f
#define RWIN  2
#define GUARD 9.0f               // (RWIN+1)^2 exactness guard
#define RPB   4                  // rows per block in the row kernel
#define NROWBLK (IMGS * H / RPB) // 1024

// ---- scratch (static __device__ arrays; allocation-free per harness rules) ----
__device__ float  s_buf[TOTAL];    // signed squared vertical distance: +v^2 (fg) / -v^2 (bg)
__device__ float  d_maxabs[IMGS];
__device__ int    d_counts[IMGS];
__device__ double d_S[IMGS];
__device__ unsigned int d_done;    // completion counter for fused finalize

__device__ __forceinline__ float sqrt_approx(float x) {
    float r;
    asm("sqrt.approx.f32 %0, %1;" : "=f"(r) : "f"(x));
    return r;
}

// ---------------------------------------------------------------------------
// Vertical EDT pass. 128 blocks x 256 threads: each thread owns a 32-row
// segment of one column; bitmask loads (full MLP), clz/ffs segment summaries
// combined in shared, 32-step unrolled SEL chains. Output: signed v^2.
__global__ void col_pass_kernel(const float* __restrict__ target) {
    __shared__ int sHiF[8][32], sHiB[8][32];
    __shared__ int sLoF[8][32], sLoB[8][32];

    int blk   = blockIdx.x;
    int tid   = threadIdx.x;
    int b     = blk >> 3;
    int chunk = blk & 7;
    int t     = tid & 31;      // local column
    int w     = tid >> 5;      // 32-row segment
    int x     = chunk * 32 + t;
    int ybase = w * 32;

    const float* m = target + b * NPIX + x;
    unsigned word = 0;
    #pragma unroll
    for (int j = 0; j < 32; j++)
        if (m[(ybase + j) * W] > 0.5f) word |= (1u << j);
    int cnt = __popc(word);

    unsigned nw = ~word;
    sHiF[w][t] = word ? (ybase + 31 - __clz(word)) : -1000000;
    sHiB[w][t] = nw   ? (ybase + 31 - __clz(nw))   : -1000000;
    sLoF[w][t] = word ? (ybase + __ffs(word) - 1)  :  1000000;
    sLoB[w][t] = nw   ? (ybase + __ffs(nw) - 1)    :  1000000;
    __syncthreads();

    int lastf = -1000000, lastb = -1000000;
    for (int w2 = 0; w2 < w; w2++) {
        lastf = max(lastf, sHiF[w2][t]);
        lastb = max(lastb, sHiB[w2][t]);
    }
    int nextf = 1000000, nextb = 1000000;
    for (int w2 = w + 1; w2 < 8; w2++) {
        nextf = min(nextf, sLoF[w2][t]);
        nextb = min(nextb, sLoB[w2][t]);
    }

    // forward chain: distance to nearest opposite-class pixel above (u16 packed)
    unsigned pk[16];
    #pragma unroll
    for (int j = 0; j < 32; j++) {
        int  y  = ybase + j;
        bool fg = (word >> j) & 1;
        int  da = y - (fg ? lastb : lastf);
        if (da > 1000) da = 1000;
        if (j & 1) pk[j >> 1] |= ((unsigned)da << 16);
        else       pk[j >> 1]  =  (unsigned)da;
        if (fg) lastf = y; else lastb = y;
    }
    // backward chain + combine + store signed v^2
    float* sbp = s_buf + b * NPIX + x;
    #pragma unroll
    for (int j = 31; j >= 0; j--) {
        int  y  = ybase + j;
        bool fg = (word >> j) & 1;
        int  db = (fg ? nextb : nextf) - y;
        if (fg) nextf = y; else nextb = y;
        int da = (int)((pk[j >> 1] >> ((j & 1) * 16)) & 0xffffu);
        int d  = min(da, db);
        float v2 = (d > 255) ? BIG2 : (float)(d * d);
        sbp[y * W] = fg ? v2 : -v2;
    }

    #pragma unroll
    for (int o = 16; o; o >>= 1) cnt += __shfl_xor_sync(0xffffffffu, cnt, o);
    if (t == 0) atomicAdd(&d_counts[b], cnt);
}

// ---------------------------------------------------------------------------
// Fused row min-plus + sigmoid + per-image reduction + last-block finalize.
// 4 rows per block, 4 pixels per thread (R7-validated structure). Candidate
// value for pixel of class sign sg:  g_c[q] + k^2 = max(sg*s[q] + k^2, k^2).
// Window |x-q| <= 2, exactness guard 9 (excluded q contribute >= 9);
// edge-replicated halo entries are dominated; rare exact full-row fallback.
__global__ void row_fused_kernel(const float* __restrict__ pred, float* __restrict__ out) {
    int blk  = blockIdx.x;
    int b    = blk >> 6;                 // 64 blocks per image
    int y0   = (blk & 63) * RPB;
    int tid  = threadIdx.x;
    int r    = tid >> 6;                 // row within block: 0..3
    int c    = tid & 63;                 // pixel-quad within row
    int base = b * NPIX + (y0 + r) * W;
    int x0   = c * 4;

    __shared__ float sh[RPB][W + 8];     // signed s tiles, +4 halo each side
    __shared__ float wred[16];           // 8 warp maxes + 8 warp sums
    __shared__ int   is_last;

    float4 s4 = *(const float4*)(s_buf + base + x0);
    *(float4*)&sh[r][x0 + 4] = s4;
    if (c == 0)  { sh[r][0] = s4.x; sh[r][1] = s4.x; sh[r][2] = s4.x; sh[r][3] = s4.x; }
    if (c == 63) { sh[r][W+4] = s4.w; sh[r][W+5] = s4.w; sh[r][W+6] = s4.w; sh[r][W+7] = s4.w; }
    float4 p4 = *(const float4*)(pred + base + x0);
    __syncthreads();

    // v[i] = sh[r][x0 + i], i=0..11 covers logical offsets -4..+7 (need -2..+5)
    float v[12];
    #pragma unroll
    for (int i = 0; i < 3; i++) {
        float4 a = *(const float4*)&sh[r][x0 + 4 * i];
        v[4*i] = a.x; v[4*i+1] = a.y; v[4*i+2] = a.z; v[4*i+3] = a.w;
    }
    float pr[4] = {p4.x, p4.y, p4.z, p4.w};

    float term = 0.f, amax = 0.f;
    #pragma unroll
    for (int p = 0; p < 4; p++) {
        float s_own = v[p + 4];
        float sg    = (s_own > 0.f) ? 1.f : -1.f;       // +1 fg, -1 bg
        float bmin  = BIGF;
        #pragma unroll
        for (int j = 0; j < 5; j++) {                   // q = x + (j-2)
            float kk = (float)((j - 2) * (j - 2));
            bmin = fminf(bmin, fmaxf(fmaf(sg, v[p + 2 + j], kk), kk));
        }
        if (bmin > GUARD) {                             // rare exact full-row fallback
            float xp = (float)(x0 + p);
            bmin = BIGF;
            #pragma unroll 1
            for (int q = 0; q < W; q++) {
                float dx = xp - (float)q;
                float kk = dx * dx;
                bmin = fminf(bmin, fmaxf(fmaf(sg, sh[r][q + 4], kk), kk));
            }
        }
        float sd   = sqrt_approx(bmin);                 // bmin >= 1 always
        amax       = fmaxf(amax, sd);
        float prob = __fdividef(1.f, 1.f + __expf(-pr[p]));
        float sds  = (s_own > 0.f) ? -sd : sd;          // signed distance
        term       = fmaf(prob, sds, term);
    }

    #pragma unroll
    for (int o = 16; o; o >>= 1) {
        amax = fmaxf(amax, __shfl_xor_sync(0xffffffffu, amax, o));
        term +=            __shfl_xor_sync(0xffffffffu, term, o);
    }
    int lane = tid & 31, wp = tid >> 5;
    if (lane == 0) { wred[wp] = amax; wred[8 + wp] = term; }
    __syncthreads();

    if (tid == 0) {
        float  mx = wred[0];
        double sm = (double)wred[8];
        #pragma unroll
        for (int i = 1; i < 8; i++) { mx = fmaxf(mx, wred[i]); sm += (double)wred[8 + i]; }
        atomicMax((int*)&d_maxabs[b], __float_as_int(mx));   // non-neg floats order as ints
        atomicAdd(&d_S[b], sm);
        __threadfence();
        unsigned int old = atomicAdd(&d_done, 1u);
        is_last = (old == (unsigned)(NROWBLK - 1)) ? 1 : 0;
    }
    __syncthreads();

    if (is_last) {
        __threadfence();
        double contrib = 0.0;
        if (tid < IMGS) {
            int    cc = __ldcg(&d_counts[tid]);
            float  mx = __ldcg(&d_maxabs[tid]);
            double S  = __ldcg(&d_S[tid]);
            if (cc > 0 && cc < NPIX)
                contrib = S / ((double)mx + 1e-6);
        }
        if (tid < 32) {
            #pragma unroll
            for (int o = 16; o; o >>= 1)
                contrib += __shfl_xor_sync(0xffffffffu, contrib, o);
            if (tid == 0) *out = (float)(contrib / (double)TOTAL);
        }
        // reset accumulators for the next graph replay
        if (tid < IMGS) { d_S[tid] = 0.0; d_maxabs[tid] = 0.0f; d_counts[tid] = 0; }
        if (tid == 0)   d_done = 0u;
    }
}

// ---------------------------------------------------------------------------
extern "C" void kernel_launch(void* const* d_in, const int* in_sizes, int n_in,
                              void* d_out, int out_size) {
    const float* pred   = (const float*)d_in[0];
    const float* target = (const float*)d_in[1];
    float* out = (float*)d_out;

    col_pass_kernel<<<IMGS * 8, 256>>>(target);
    row_fused_kernel<<<NROWBLK, 256>>>(pred, out);
}